// round 14
// baseline (speedup 1.0000x reference)
#include <cuda_runtime.h>
#include <cuda_bf16.h>
#include <math.h>
#include <stdint.h>

// Problem dims
#define BB   32
#define LL   512
#define EE   768
#define HH   1024
#define OO   128
#define BL   (BB * LL)          // 16384

// ---------------------------------------------------------------------------
// Static scratch (allocation-free)
// ---------------------------------------------------------------------------
__device__ float g_xp[(size_t)BL * HH];
__device__ float g_r1[(size_t)BL * HH];
__device__ float g_r2[(size_t)BL * HH];

// per-block done flags (R8 layout)
__device__ unsigned g_done[4 * 16 * 32];

#define SEL_EXT 0
#define SEL_R1  1
#define SEL_R2  2
#define SEL_XP  3

__device__ __forceinline__ const float* pick_src(int sel, const float* ext) {
    if (sel == SEL_R1) return g_r1;
    if (sel == SEL_R2) return g_r2;
    if (sel == SEL_XP) return g_xp;
    return ext;
}
__device__ __forceinline__ float* pick_dst(int sel, float* ext) {
    if (sel == SEL_XP) return g_xp;
    if (sel == SEL_R1) return g_r1;
    if (sel == SEL_R2) return g_r2;
    return ext;
}

// ---------------------------------------------------------------------------
// helpers
// ---------------------------------------------------------------------------
__device__ __forceinline__ uint32_t smem_to_u32(const void* p) {
    uint32_t a;
    asm("{ .reg .u64 t; cvta.to.shared.u64 t, %1; cvt.u32.u64 %0, t; }"
        : "=r"(a) : "l"(p));
    return a;
}
__device__ __forceinline__ float fast_tanh(float x) {
    float xc = fminf(fmaxf(x, -15.0f), 15.0f);
    float e  = __expf(2.0f * xc);
    return 1.0f - __fdividef(2.0f, e + 1.0f);
}
__device__ __forceinline__ void st_release(unsigned* p, unsigned v) {
    asm volatile("st.global.release.gpu.u32 [%0], %1;" :: "l"(p), "r"(v) : "memory");
}
__device__ __forceinline__ unsigned ld_acquire(const unsigned* p) {
    unsigned v;
    asm volatile("ld.global.acquire.gpu.u32 %0, [%1];" : "=r"(v) : "l"(p) : "memory");
    return v;
}

// ldmatrix / mma.sync (sm_80-baseline ISA)
#define LDSM4(r, a) \
    asm volatile("ldmatrix.sync.aligned.m8n8.x4.shared.b16 {%0,%1,%2,%3}, [%4];" \
        : "=r"((r)[0]), "=r"((r)[1]), "=r"((r)[2]), "=r"((r)[3]) : "r"(a))
#define LDSM2(r, a) \
    asm volatile("ldmatrix.sync.aligned.m8n8.x2.shared.b16 {%0,%1}, [%2];" \
        : "=r"((r)[0]), "=r"((r)[1]) : "r"(a))
#define MMA16816(d, a, b) \
    asm volatile("mma.sync.aligned.m16n8k16.row.col.f32.bf16.bf16.f32 " \
        "{%0,%1,%2,%3}, {%4,%5,%6,%7}, {%8,%9}, {%0,%1,%2,%3};" \
        : "+f"((d)[0]), "+f"((d)[1]), "+f"((d)[2]), "+f"((d)[3]) \
        : "r"((a)[0]), "r"((a)[1]), "r"((a)[2]), "r"((a)[3]), \
          "r"((b)[0]), "r"((b)[1]))

// 8 fp32 -> 8 bf16 hi (uint4) + 8 bf16 lo (uint4)
__device__ __forceinline__ void split8(const float4 v0, const float4 v1,
                                       uint4& hh, uint4& ll)
{
    float f[8] = {v0.x, v0.y, v0.z, v0.w, v1.x, v1.y, v1.z, v1.w};
    __nv_bfloat162 h[4], l[4];
    #pragma unroll
    for (int i = 0; i < 4; i++) {
        __nv_bfloat16 h0 = __float2bfloat16(f[2*i]);
        __nv_bfloat16 h1 = __float2bfloat16(f[2*i+1]);
        h[i] = __nv_bfloat162(h0, h1);
        l[i] = __nv_bfloat162(__float2bfloat16(f[2*i]   - __bfloat162float(h0)),
                              __float2bfloat16(f[2*i+1] - __bfloat162float(h1)));
    }
    hh = *(uint4*)h;
    ll = *(uint4*)l;
}

// 4 fp32 -> 4 bf16 hi (uint2) + 4 bf16 lo (uint2)
__device__ __forceinline__ void split4(const float4 v, uint2& hh, uint2& ll)
{
    __nv_bfloat16 h0 = __float2bfloat16(v.x);
    __nv_bfloat16 h1 = __float2bfloat16(v.y);
    __nv_bfloat16 h2 = __float2bfloat16(v.z);
    __nv_bfloat16 h3 = __float2bfloat16(v.w);
    __nv_bfloat162 hp0(h0, h1), hp1(h2, h3);
    __nv_bfloat162 lp0(__float2bfloat16(v.x - __bfloat162float(h0)),
                       __float2bfloat16(v.y - __bfloat162float(h1)));
    __nv_bfloat162 lp1(__float2bfloat16(v.z - __bfloat162float(h2)),
                       __float2bfloat16(v.w - __bfloat162float(h3)));
    hh.x = *(uint32_t*)&hp0; hh.y = *(uint32_t*)&hp1;
    ll.x = *(uint32_t*)&lp0; ll.y = *(uint32_t*)&lp1;
}

// ---------------------------------------------------------------------------
// HMMA GEMM: C[M,Nfull] = A[M,K] @ B[Nfull,K]^T + bias1 (+bias2)
// K-chunk 64 (was 32): half the sync epochs; dynamic smem 73.7KB, GPAD 72
// (144B row stride -> LDSM row addrs hit distinct bank phases).
// gridDim.z = 2 selects an alternate (A,B,bias,C) set to fuse the two heads.
// ---------------------------------------------------------------------------
#define GKC  64
#define GPAD 72
#define GEMM_TILE (128 * GPAD)                 // bf16 per tile
#define GEMM_SMEM_BYTES (4 * GEMM_TILE * 2)    // 73728

__global__ __launch_bounds__(256) void mma_gemm(
    const float* __restrict__ Aext, int Asel,
    const float* __restrict__ B,
    float* __restrict__ Cext, int Csel,
    const float* __restrict__ bias1, const float* __restrict__ bias2,
    int Nfull, int K,
    int AselZ, const float* __restrict__ Bz,
    const float* __restrict__ biasz, float* __restrict__ Cz)
{
    const float* A = pick_src(Asel, Aext);
    float* C = pick_dst(Csel, Cext);
    if (blockIdx.z == 1) {       // fused second head
        A = pick_src(AselZ, nullptr);
        B = Bz;
        bias1 = biasz;
        C = Cz;
    }

    extern __shared__ __nv_bfloat16 gsm[];
    __nv_bfloat16* sAh = gsm;
    __nv_bfloat16* sAl = gsm + GEMM_TILE;
    __nv_bfloat16* sBh = gsm + 2 * GEMM_TILE;
    __nv_bfloat16* sBl = gsm + 3 * GEMM_TILE;

    const int tid  = threadIdx.x;
    const int wid  = tid >> 5;
    const int lane = tid & 31;
    const int wm   = wid >> 2;
    const int wn   = wid & 3;
    const int m0   = blockIdx.y * 128;
    const int n0   = blockIdx.x * 128;

    float acc[4][4][4];
    #pragma unroll
    for (int i = 0; i < 4; i++)
        #pragma unroll
        for (int j = 0; j < 4; j++)
            #pragma unroll
            for (int k = 0; k < 4; k++) acc[i][j][k] = 0.0f;

    const uint32_t uAh = smem_to_u32(sAh), uAl = smem_to_u32(sAl);
    const uint32_t uBh = smem_to_u32(sBh), uBl = smem_to_u32(sBl);
    const uint32_t aoff = (uint32_t)((wm * 64 + (lane & 15)) * GPAD + (lane >> 4) * 8) * 2u;
    const uint32_t boff = (uint32_t)((wn * 32 + (lane & 7)) * GPAD + ((lane >> 3) & 1) * 8) * 2u;

    for (int k0 = 0; k0 < K; k0 += GKC) {
        // stage + split: 1024 8-float pieces for A, 1024 for B; 16 per thread
        #pragma unroll 4
        for (int p = 0; p < 16; p++) {
            const int i   = p * 256 + tid;
            const int j   = i & 1023;
            const int row = j >> 3;              // 0..127
            const int seg = j & 7;               // 8-float segment
            const int so  = row * GPAD + seg * 8;
            if (p < 8) {
                const float* src = A + (size_t)(m0 + row) * K + k0 + seg * 8;
                float4 v0 = *(const float4*)src;
                float4 v1 = *(const float4*)(src + 4);
                uint4 hh, ll;
                split8(v0, v1, hh, ll);
                *(uint4*)&sAh[so] = hh;
                *(uint4*)&sAl[so] = ll;
            } else {
                const float* src = B + (size_t)(n0 + row) * K + k0 + seg * 8;
                float4 v0 = *(const float4*)src;
                float4 v1 = *(const float4*)(src + 4);
                uint4 hh, ll;
                split8(v0, v1, hh, ll);
                *(uint4*)&sBh[so] = hh;
                *(uint4*)&sBl[so] = ll;
            }
        }
        __syncthreads();

        #pragma unroll
        for (int ks = 0; ks < 4; ks++) {
            const uint32_t ko = (uint32_t)(ks * 16) * 2u;
            uint32_t bh[4][2], bl[4][2];
            #pragma unroll
            for (int nf = 0; nf < 4; nf++) {
                const uint32_t fo = (uint32_t)(nf * 8 * GPAD) * 2u + ko;
                LDSM2(bh[nf], uBh + boff + fo);
                LDSM2(bl[nf], uBl + boff + fo);
            }
            #pragma unroll
            for (int mf = 0; mf < 4; mf++) {
                const uint32_t fo = (uint32_t)(mf * 16 * GPAD) * 2u + ko;
                uint32_t ah[4], al[4];
                LDSM4(ah, uAh + aoff + fo);
                LDSM4(al, uAl + aoff + fo);
                #pragma unroll
                for (int nf = 0; nf < 4; nf++) {
                    MMA16816(acc[mf][nf], ah, bh[nf]);
                    MMA16816(acc[mf][nf], ah, bl[nf]);
                    MMA16816(acc[mf][nf], al, bh[nf]);
                }
            }
        }
        __syncthreads();
    }

    #pragma unroll
    for (int mf = 0; mf < 4; mf++) {
        const int mrow = m0 + wm * 64 + mf * 16 + (lane >> 2);
        #pragma unroll
        for (int nf = 0; nf < 4; nf++) {
            const int col = n0 + wn * 32 + nf * 8 + (lane & 3) * 2;
            float b0 = bias1[col], b1 = bias1[col + 1];
            if (bias2) { b0 += bias2[col]; b1 += bias2[col + 1]; }
            float2 v0 = make_float2(acc[mf][nf][0] + b0, acc[mf][nf][1] + b1);
            float2 v1 = make_float2(acc[mf][nf][2] + b0, acc[mf][nf][3] + b1);
            *(float2*)(C + (size_t)mrow * Nfull + col) = v0;
            *(float2*)(C + (size_t)(mrow + 8) * Nfull + col) = v1;
        }
    }
}

// ---------------------------------------------------------------------------
// Persistent RNN layer with HMMA inner product (byte-identical to R13 pass)
// ---------------------------------------------------------------------------
#define RNN_BLOCKS 128
#define RNN_SMEM_BYTES (32 * 1028 * 4)   // 131.6KB -> forces 1 block/SM
#define IMG_PAD 1032                     // bf16 per image row
#define HW_PAD  72                       // bf16 per h row (64 data + 8 pad)
#define HW_WARP (8 * HW_PAD * 2)         // bytes per warp per (hi|lo): 1152
#define PSM_STRIDE 296                   // floats per warp region
#define PSM_OFF 40960                    // byte offset of psm (> 16*2304)

__global__ __launch_bounds__(512) void rnn_layer_kernel(
    int rsel, const float* __restrict__ W)
{
    float* r = (rsel == SEL_R1) ? g_r1 : g_r2;

    extern __shared__ char smc[];

    const int tid  = threadIdx.x;
    const int warp = tid >> 5;
    const int lane = tid & 31;
    const int bg = blockIdx.x >> 5;
    const int cg = blockIdx.x & 31;
    const int b0 = bg * 8;
    const int c0 = cg * 32;
    const int kbase = warp * 64;

    unsigned* my_flag   = &g_done[(bg * 16 + (cg >> 1)) * 32 + (cg & 1)];
    unsigned* poll_line = &g_done[(bg * 16 + warp) * 32];

    // ---- build W_hh bf16 hi/lo fragments in registers (once per layer) ----
    uint32_t wh[2][4][4], wl[2][4][4];
    {
        __nv_bfloat16* img_h = (__nv_bfloat16*)smc;
        __nv_bfloat16* img_l = (__nv_bfloat16*)(smc + 16 * IMG_PAD * 2);
        const uint32_t uih = smem_to_u32(img_h);
        const uint32_t uil = smem_to_u32(img_l);

        #pragma unroll
        for (int mf = 0; mf < 2; mf++) {
            const int row = tid >> 5;            // 0..15
            const int kk0 = (tid & 31) * 32;
            const float* wsrc = W + (size_t)(c0 + mf * 16 + row) * HH + kk0;
            #pragma unroll
            for (int j = 0; j < 8; j++) {
                float4 v = *(const float4*)(wsrc + j * 4);
                uint2 hh, ll;
                split4(v, hh, ll);
                *(uint2*)&img_h[row * IMG_PAD + kk0 + j * 4] = hh;
                *(uint2*)&img_l[row * IMG_PAD + kk0 + j * 4] = ll;
            }
            __syncthreads();
            const uint32_t ao =
                (uint32_t)((lane & 15) * IMG_PAD + kbase + (lane >> 4) * 8) * 2u;
            #pragma unroll
            for (int ks = 0; ks < 4; ks++) {
                LDSM4(wh[mf][ks], uih + ao + (uint32_t)(ks * 16) * 2u);
                LDSM4(wl[mf][ks], uil + ao + (uint32_t)(ks * 16) * 2u);
            }
            __syncthreads();
        }
    }

    // steady-state smem: h rows (16 warps x 2304B = 36864B) + psm
    char* hwbase = smc;
    float* psm   = (float*)(smc + PSM_OFF);
    __nv_bfloat16* hw_h = (__nv_bfloat16*)(hwbase + warp * (2 * HW_WARP));
    __nv_bfloat16* hw_l = (__nv_bfloat16*)(hwbase + warp * (2 * HW_WARP) + HW_WARP);
    const uint32_t uhh = smem_to_u32(hw_h);
    const uint32_t uhl = smem_to_u32(hw_l);
    const uint32_t bo =
        (uint32_t)((lane & 7) * HW_PAD + ((lane >> 3) & 1) * 8) * 2u;

    const float* xp_ptr = g_xp + ((size_t)(b0 + warp) * LL) * HH + (c0 + lane);
    float*       r_ptr  = r    + ((size_t)(b0 + warp) * LL) * HH + (c0 + lane);

    for (int t = 0; t < LL; t++) {
        float xq = 0.0f;
        if (t > 0) {
            unsigned f;
            do {
                unsigned v = (lane < 2) ? ld_acquire(poll_line + lane) : 0u;
                unsigned f0 = __shfl_sync(0xffffffffu, v, 0);
                unsigned f1 = __shfl_sync(0xffffffffu, v, 1);
                f = (f0 < f1) ? f0 : f1;
            } while (f < (unsigned)t);

            const float* hsrc = r + (size_t)(t - 1) * HH + kbase;
            #pragma unroll
            for (int j = 0; j < 4; j++) {
                const int i  = j * 32 + lane;
                const int rr = i >> 4;            // 0..7 (batch row)
                const int qq = (i & 15) << 2;     // 0..60 (k)
                float4 v = *(const float4*)(hsrc + (size_t)(b0 + rr) * LL * HH + qq);
                uint2 hh, ll;
                split4(v, hh, ll);
                *(uint2*)&hw_h[rr * HW_PAD + qq] = hh;
                *(uint2*)&hw_l[rr * HW_PAD + qq] = ll;
            }
            __syncwarp();

            if (warp < 8) xq = __ldg(xp_ptr + (size_t)t * HH);

            float acc[2][4];
            #pragma unroll
            for (int mf = 0; mf < 2; mf++)
                #pragma unroll
                for (int i = 0; i < 4; i++) acc[mf][i] = 0.0f;

            #pragma unroll
            for (int ks = 0; ks < 4; ks++) {
                uint32_t bh[2], bl[2];
                const uint32_t ko = (uint32_t)(ks * 16) * 2u;
                LDSM2(bh, uhh + bo + ko);
                LDSM2(bl, uhl + bo + ko);
                #pragma unroll
                for (int mf = 0; mf < 2; mf++) {
                    MMA16816(acc[mf], wh[mf][ks], bh);
                    MMA16816(acc[mf], wh[mf][ks], bl);
                    MMA16816(acc[mf], wl[mf][ks], bh);
                }
            }

            #pragma unroll
            for (int mf = 0; mf < 2; mf++) {
                const int m = mf * 16 + (lane >> 2);
                const int n = (lane & 3) * 2;
                float* pw = psm + warp * PSM_STRIDE;
                pw[m * 9 + n]           = acc[mf][0];
                pw[m * 9 + n + 1]       = acc[mf][1];
                pw[(m + 8) * 9 + n]     = acc[mf][2];
                pw[(m + 8) * 9 + n + 1] = acc[mf][3];
            }
            __syncthreads();
        } else {
            if (warp < 8) xq = __ldg(xp_ptr);
        }

        if (warp < 8) {
            float dot = 0.0f;
            if (t > 0) {
                #pragma unroll
                for (int w = 0; w < 16; w++)
                    dot += psm[w * PSM_STRIDE + lane * 9 + warp];
            }
            r_ptr[(size_t)t * HH] = fast_tanh(xq + dot);

            if (t < LL - 1) {
                asm volatile("bar.sync 1, 256;" ::: "memory");
                if (tid == 0)
                    st_release(my_flag, (unsigned)(t + 1));
            }
        }
    }
}

__global__ void rnn_init_kernel()
{
    const int i = threadIdx.x;
    if (i < 128) g_done[(i >> 1) * 32 + (i & 1)] = 0u;
}

// ---------------------------------------------------------------------------
// Launch: 7 graph nodes
// ---------------------------------------------------------------------------
extern "C" void kernel_launch(void* const* d_in, const int* in_sizes, int n_in,
                              void* d_out, int out_size)
{
    const float* x     = (const float*)d_in[0];
    const float* W_ih1 = (const float*)d_in[1];
    const float* W_hh1 = (const float*)d_in[2];
    const float* b_ih1 = (const float*)d_in[3];
    const float* b_hh1 = (const float*)d_in[4];
    const float* W_ih2 = (const float*)d_in[5];
    const float* W_hh2 = (const float*)d_in[6];
    const float* b_ih2 = (const float*)d_in[7];
    const float* b_hh2 = (const float*)d_in[8];
    const float* W1    = (const float*)d_in[9];
    const float* b1    = (const float*)d_in[10];
    const float* W2    = (const float*)d_in[11];
    const float* b2    = (const float*)d_in[12];
    float* out = (float*)d_out;

    static int attr_set = 0;
    if (!attr_set) {
        cudaFuncSetAttribute(rnn_layer_kernel,
                             cudaFuncAttributeMaxDynamicSharedMemorySize,
                             RNN_SMEM_BYTES);
        cudaFuncSetAttribute(mma_gemm,
                             cudaFuncAttributeMaxDynamicSharedMemorySize,
                             GEMM_SMEM_BYTES);
        attr_set = 1;
    }

    const dim3 gBig(HH / 128, BL / 128, 1);   // (8, 128, 1)
    const dim3 gHead(OO / 128, BL / 128, 2);  // (1, 128, 2) both heads fused

    // xp = x @ W_ih1^T + b_ih1 + b_hh1
    mma_gemm<<<gBig, 256, GEMM_SMEM_BYTES>>>(
        x, SEL_EXT, W_ih1, nullptr, SEL_XP, b_ih1, b_hh1, HH, EE,
        0, nullptr, nullptr, nullptr);
    // layer 1 recurrence
    rnn_init_kernel<<<1, 128>>>();
    rnn_layer_kernel<<<RNN_BLOCKS, 512, RNN_SMEM_BYTES>>>(SEL_R1, W_hh1);

    // xp = r1 @ W_ih2^T + b_ih2 + b_hh2
    mma_gemm<<<gBig, 256, GEMM_SMEM_BYTES>>>(
        nullptr, SEL_R1, W_ih2, nullptr, SEL_XP, b_ih2, b_hh2, HH, HH,
        0, nullptr, nullptr, nullptr);
    // layer 2 recurrence
    rnn_init_kernel<<<1, 128>>>();
    rnn_layer_kernel<<<RNN_BLOCKS, 512, RNN_SMEM_BYTES>>>(SEL_R2, W_hh2);

    // both heads in one launch: z=0 -> y = r1@W1^T + b1 ; z=1 -> z = r2@W2^T + b2
    mma_gemm<<<gHead, 256, GEMM_SMEM_BYTES>>>(
        nullptr, SEL_R1, W1, out, SEL_EXT, b1, nullptr, OO, HH,
        SEL_R2, W2, b2, out + (size_t)BL * OO);
}

// round 15
// speedup vs baseline: 1.2036x; 1.2036x over previous
#include <cuda_runtime.h>
#include <cuda_bf16.h>
#include <math.h>
#include <stdint.h>

// Problem dims
#define BB   32
#define LL   512
#define EE   768
#define HH   1024
#define OO   128
#define BL   (BB * LL)          // 16384

// ---------------------------------------------------------------------------
// Static scratch (allocation-free)
// ---------------------------------------------------------------------------
__device__ float g_xp[(size_t)BL * HH];
__device__ float g_r1[(size_t)BL * HH];
__device__ float g_r2[(size_t)BL * HH];

// per-block done flags (R8 layout)
__device__ unsigned g_done[4 * 16 * 32];

#define SEL_EXT 0
#define SEL_R1  1
#define SEL_R2  2
#define SEL_XP  3

__device__ __forceinline__ const float* pick_src(int sel, const float* ext) {
    if (sel == SEL_R1) return g_r1;
    if (sel == SEL_R2) return g_r2;
    if (sel == SEL_XP) return g_xp;
    return ext;
}
__device__ __forceinline__ float* pick_dst(int sel, float* ext) {
    if (sel == SEL_XP) return g_xp;
    if (sel == SEL_R1) return g_r1;
    if (sel == SEL_R2) return g_r2;
    return ext;
}

// ---------------------------------------------------------------------------
// helpers
// ---------------------------------------------------------------------------
__device__ __forceinline__ uint32_t smem_to_u32(const void* p) {
    uint32_t a;
    asm("{ .reg .u64 t; cvta.to.shared.u64 t, %1; cvt.u32.u64 %0, t; }"
        : "=r"(a) : "l"(p));
    return a;
}
__device__ __forceinline__ float fast_tanh(float x) {
    float xc = fminf(fmaxf(x, -15.0f), 15.0f);
    float e  = __expf(2.0f * xc);
    return 1.0f - __fdividef(2.0f, e + 1.0f);
}
__device__ __forceinline__ void st_release(unsigned* p, unsigned v) {
    asm volatile("st.global.release.gpu.u32 [%0], %1;" :: "l"(p), "r"(v) : "memory");
}
__device__ __forceinline__ unsigned ld_acquire(const unsigned* p) {
    unsigned v;
    asm volatile("ld.global.acquire.gpu.u32 %0, [%1];" : "=r"(v) : "l"(p) : "memory");
    return v;
}

// ldmatrix / mma.sync (sm_80-baseline ISA)
#define LDSM4(r, a) \
    asm volatile("ldmatrix.sync.aligned.m8n8.x4.shared.b16 {%0,%1,%2,%3}, [%4];" \
        : "=r"((r)[0]), "=r"((r)[1]), "=r"((r)[2]), "=r"((r)[3]) : "r"(a))
#define LDSM2(r, a) \
    asm volatile("ldmatrix.sync.aligned.m8n8.x2.shared.b16 {%0,%1}, [%2];" \
        : "=r"((r)[0]), "=r"((r)[1]) : "r"(a))
#define MMA16816(d, a, b) \
    asm volatile("mma.sync.aligned.m16n8k16.row.col.f32.bf16.bf16.f32 " \
        "{%0,%1,%2,%3}, {%4,%5,%6,%7}, {%8,%9}, {%0,%1,%2,%3};" \
        : "+f"((d)[0]), "+f"((d)[1]), "+f"((d)[2]), "+f"((d)[3]) \
        : "r"((a)[0]), "r"((a)[1]), "r"((a)[2]), "r"((a)[3]), \
          "r"((b)[0]), "r"((b)[1]))

// 8 fp32 -> 8 bf16 hi (uint4) + 8 bf16 lo (uint4)
__device__ __forceinline__ void split8(const float4 v0, const float4 v1,
                                       uint4& hh, uint4& ll)
{
    float f[8] = {v0.x, v0.y, v0.z, v0.w, v1.x, v1.y, v1.z, v1.w};
    __nv_bfloat162 h[4], l[4];
    #pragma unroll
    for (int i = 0; i < 4; i++) {
        __nv_bfloat16 h0 = __float2bfloat16(f[2*i]);
        __nv_bfloat16 h1 = __float2bfloat16(f[2*i+1]);
        h[i] = __nv_bfloat162(h0, h1);
        l[i] = __nv_bfloat162(__float2bfloat16(f[2*i]   - __bfloat162float(h0)),
                              __float2bfloat16(f[2*i+1] - __bfloat162float(h1)));
    }
    hh = *(uint4*)h;
    ll = *(uint4*)l;
}

// 4 fp32 -> 4 bf16 hi (uint2) + 4 bf16 lo (uint2)
__device__ __forceinline__ void split4(const float4 v, uint2& hh, uint2& ll)
{
    __nv_bfloat16 h0 = __float2bfloat16(v.x);
    __nv_bfloat16 h1 = __float2bfloat16(v.y);
    __nv_bfloat16 h2 = __float2bfloat16(v.z);
    __nv_bfloat16 h3 = __float2bfloat16(v.w);
    __nv_bfloat162 hp0(h0, h1), hp1(h2, h3);
    __nv_bfloat162 lp0(__float2bfloat16(v.x - __bfloat162float(h0)),
                       __float2bfloat16(v.y - __bfloat162float(h1)));
    __nv_bfloat162 lp1(__float2bfloat16(v.z - __bfloat162float(h2)),
                       __float2bfloat16(v.w - __bfloat162float(h3)));
    hh.x = *(uint32_t*)&hp0; hh.y = *(uint32_t*)&hp1;
    ll.x = *(uint32_t*)&lp0; ll.y = *(uint32_t*)&lp1;
}

// ---------------------------------------------------------------------------
// HMMA GEMM — R13-proven configuration (GKC=32, GPAD=40, STATIC smem 41KB,
// 2 CTAs/SM). gridDim.z = 2 selects an alternate (A,B,bias,C) set so the two
// head GEMMs run in one launch; z=1 only swaps pointers at entry.
// ---------------------------------------------------------------------------
#define GKC  32
#define GPAD 40

__global__ __launch_bounds__(256) void mma_gemm(
    const float* __restrict__ Aext, int Asel,
    const float* __restrict__ B,
    float* __restrict__ Cext, int Csel,
    const float* __restrict__ bias1, const float* __restrict__ bias2,
    int Nfull, int K,
    int AselZ, const float* __restrict__ Bz,
    const float* __restrict__ biasz, float* __restrict__ Cz)
{
    const float* A = pick_src(Asel, Aext);
    float* C = pick_dst(Csel, Cext);
    if (blockIdx.z == 1) {       // fused second head
        A = pick_src(AselZ, nullptr);
        B = Bz;
        bias1 = biasz;
        C = Cz;
    }

    __shared__ __nv_bfloat16 sAh[128 * GPAD], sAl[128 * GPAD];
    __shared__ __nv_bfloat16 sBh[128 * GPAD], sBl[128 * GPAD];

    const int tid  = threadIdx.x;
    const int wid  = tid >> 5;
    const int lane = tid & 31;
    const int wm   = wid >> 2;
    const int wn   = wid & 3;
    const int m0   = blockIdx.y * 128;
    const int n0   = blockIdx.x * 128;

    float acc[4][4][4];
    #pragma unroll
    for (int i = 0; i < 4; i++)
        #pragma unroll
        for (int j = 0; j < 4; j++)
            #pragma unroll
            for (int k = 0; k < 4; k++) acc[i][j][k] = 0.0f;

    const uint32_t uAh = smem_to_u32(sAh), uAl = smem_to_u32(sAl);
    const uint32_t uBh = smem_to_u32(sBh), uBl = smem_to_u32(sBl);
    const uint32_t aoff = (uint32_t)((wm * 64 + (lane & 15)) * GPAD + (lane >> 4) * 8) * 2u;
    const uint32_t boff = (uint32_t)((wn * 32 + (lane & 7)) * GPAD + ((lane >> 3) & 1) * 8) * 2u;

    for (int k0 = 0; k0 < K; k0 += GKC) {
        #pragma unroll
        for (int p = 0; p < 4; p++) {
            const int i   = p * 256 + tid;
            const int j   = i & 511;
            const int row = j >> 2;
            const int seg = j & 3;
            const int so  = row * GPAD + seg * 8;
            if (p < 2) {
                const float* src = A + (size_t)(m0 + row) * K + k0 + seg * 8;
                float4 v0 = *(const float4*)src;
                float4 v1 = *(const float4*)(src + 4);
                uint4 hh, ll;
                split8(v0, v1, hh, ll);
                *(uint4*)&sAh[so] = hh;
                *(uint4*)&sAl[so] = ll;
            } else {
                const float* src = B + (size_t)(n0 + row) * K + k0 + seg * 8;
                float4 v0 = *(const float4*)src;
                float4 v1 = *(const float4*)(src + 4);
                uint4 hh, ll;
                split8(v0, v1, hh, ll);
                *(uint4*)&sBh[so] = hh;
                *(uint4*)&sBl[so] = ll;
            }
        }
        __syncthreads();

        #pragma unroll
        for (int ks = 0; ks < 2; ks++) {
            const uint32_t ko = (uint32_t)(ks * 16) * 2u;
            uint32_t bh[4][2], bl[4][2];
            #pragma unroll
            for (int nf = 0; nf < 4; nf++) {
                const uint32_t fo = (uint32_t)(nf * 8 * GPAD) * 2u + ko;
                LDSM2(bh[nf], uBh + boff + fo);
                LDSM2(bl[nf], uBl + boff + fo);
            }
            #pragma unroll
            for (int mf = 0; mf < 4; mf++) {
                const uint32_t fo = (uint32_t)(mf * 16 * GPAD) * 2u + ko;
                uint32_t ah[4], al[4];
                LDSM4(ah, uAh + aoff + fo);
                LDSM4(al, uAl + aoff + fo);
                #pragma unroll
                for (int nf = 0; nf < 4; nf++) {
                    MMA16816(acc[mf][nf], ah, bh[nf]);
                    MMA16816(acc[mf][nf], ah, bl[nf]);
                    MMA16816(acc[mf][nf], al, bh[nf]);
                }
            }
        }
        __syncthreads();
    }

    #pragma unroll
    for (int mf = 0; mf < 4; mf++) {
        const int mrow = m0 + wm * 64 + mf * 16 + (lane >> 2);
        #pragma unroll
        for (int nf = 0; nf < 4; nf++) {
            const int col = n0 + wn * 32 + nf * 8 + (lane & 3) * 2;
            float b0 = bias1[col], b1 = bias1[col + 1];
            if (bias2) { b0 += bias2[col]; b1 += bias2[col + 1]; }
            float2 v0 = make_float2(acc[mf][nf][0] + b0, acc[mf][nf][1] + b1);
            float2 v1 = make_float2(acc[mf][nf][2] + b0, acc[mf][nf][3] + b1);
            *(float2*)(C + (size_t)mrow * Nfull + col) = v0;
            *(float2*)(C + (size_t)(mrow + 8) * Nfull + col) = v1;
        }
    }
}

// ---------------------------------------------------------------------------
// Persistent RNN layer with HMMA inner product (byte-identical to R13 pass)
// ---------------------------------------------------------------------------
#define RNN_BLOCKS 128
#define RNN_SMEM_BYTES (32 * 1028 * 4)   // 131.6KB -> forces 1 block/SM
#define IMG_PAD 1032                     // bf16 per image row
#define HW_PAD  72                       // bf16 per h row (64 data + 8 pad)
#define HW_WARP (8 * HW_PAD * 2)         // bytes per warp per (hi|lo): 1152
#define PSM_STRIDE 296                   // floats per warp region
#define PSM_OFF 40960                    // byte offset of psm (> 16*2304)

__global__ __launch_bounds__(512) void rnn_layer_kernel(
    int rsel, const float* __restrict__ W)
{
    float* r = (rsel == SEL_R1) ? g_r1 : g_r2;

    extern __shared__ char smc[];

    const int tid  = threadIdx.x;
    const int warp = tid >> 5;
    const int lane = tid & 31;
    const int bg = blockIdx.x >> 5;
    const int cg = blockIdx.x & 31;
    const int b0 = bg * 8;
    const int c0 = cg * 32;
    const int kbase = warp * 64;

    unsigned* my_flag   = &g_done[(bg * 16 + (cg >> 1)) * 32 + (cg & 1)];
    unsigned* poll_line = &g_done[(bg * 16 + warp) * 32];

    // ---- build W_hh bf16 hi/lo fragments in registers (once per layer) ----
    uint32_t wh[2][4][4], wl[2][4][4];
    {
        __nv_bfloat16* img_h = (__nv_bfloat16*)smc;
        __nv_bfloat16* img_l = (__nv_bfloat16*)(smc + 16 * IMG_PAD * 2);
        const uint32_t uih = smem_to_u32(img_h);
        const uint32_t uil = smem_to_u32(img_l);

        #pragma unroll
        for (int mf = 0; mf < 2; mf++) {
            const int row = tid >> 5;            // 0..15
            const int kk0 = (tid & 31) * 32;
            const float* wsrc = W + (size_t)(c0 + mf * 16 + row) * HH + kk0;
            #pragma unroll
            for (int j = 0; j < 8; j++) {
                float4 v = *(const float4*)(wsrc + j * 4);
                uint2 hh, ll;
                split4(v, hh, ll);
                *(uint2*)&img_h[row * IMG_PAD + kk0 + j * 4] = hh;
                *(uint2*)&img_l[row * IMG_PAD + kk0 + j * 4] = ll;
            }
            __syncthreads();
            const uint32_t ao =
                (uint32_t)((lane & 15) * IMG_PAD + kbase + (lane >> 4) * 8) * 2u;
            #pragma unroll
            for (int ks = 0; ks < 4; ks++) {
                LDSM4(wh[mf][ks], uih + ao + (uint32_t)(ks * 16) * 2u);
                LDSM4(wl[mf][ks], uil + ao + (uint32_t)(ks * 16) * 2u);
            }
            __syncthreads();
        }
    }

    // steady-state smem: h rows (16 warps x 2304B = 36864B) + psm
    char* hwbase = smc;
    float* psm   = (float*)(smc + PSM_OFF);
    __nv_bfloat16* hw_h = (__nv_bfloat16*)(hwbase + warp * (2 * HW_WARP));
    __nv_bfloat16* hw_l = (__nv_bfloat16*)(hwbase + warp * (2 * HW_WARP) + HW_WARP);
    const uint32_t uhh = smem_to_u32(hw_h);
    const uint32_t uhl = smem_to_u32(hw_l);
    const uint32_t bo =
        (uint32_t)((lane & 7) * HW_PAD + ((lane >> 3) & 1) * 8) * 2u;

    const float* xp_ptr = g_xp + ((size_t)(b0 + warp) * LL) * HH + (c0 + lane);
    float*       r_ptr  = r    + ((size_t)(b0 + warp) * LL) * HH + (c0 + lane);

    for (int t = 0; t < LL; t++) {
        float xq = 0.0f;
        if (t > 0) {
            unsigned f;
            do {
                unsigned v = (lane < 2) ? ld_acquire(poll_line + lane) : 0u;
                unsigned f0 = __shfl_sync(0xffffffffu, v, 0);
                unsigned f1 = __shfl_sync(0xffffffffu, v, 1);
                f = (f0 < f1) ? f0 : f1;
            } while (f < (unsigned)t);

            const float* hsrc = r + (size_t)(t - 1) * HH + kbase;
            #pragma unroll
            for (int j = 0; j < 4; j++) {
                const int i  = j * 32 + lane;
                const int rr = i >> 4;            // 0..7 (batch row)
                const int qq = (i & 15) << 2;     // 0..60 (k)
                float4 v = *(const float4*)(hsrc + (size_t)(b0 + rr) * LL * HH + qq);
                uint2 hh, ll;
                split4(v, hh, ll);
                *(uint2*)&hw_h[rr * HW_PAD + qq] = hh;
                *(uint2*)&hw_l[rr * HW_PAD + qq] = ll;
            }
            __syncwarp();

            if (warp < 8) xq = __ldg(xp_ptr + (size_t)t * HH);

            float acc[2][4];
            #pragma unroll
            for (int mf = 0; mf < 2; mf++)
                #pragma unroll
                for (int i = 0; i < 4; i++) acc[mf][i] = 0.0f;

            #pragma unroll
            for (int ks = 0; ks < 4; ks++) {
                uint32_t bh[2], bl[2];
                const uint32_t ko = (uint32_t)(ks * 16) * 2u;
                LDSM2(bh, uhh + bo + ko);
                LDSM2(bl, uhl + bo + ko);
                #pragma unroll
                for (int mf = 0; mf < 2; mf++) {
                    MMA16816(acc[mf], wh[mf][ks], bh);
                    MMA16816(acc[mf], wh[mf][ks], bl);
                    MMA16816(acc[mf], wl[mf][ks], bh);
                }
            }

            #pragma unroll
            for (int mf = 0; mf < 2; mf++) {
                const int m = mf * 16 + (lane >> 2);
                const int n = (lane & 3) * 2;
                float* pw = psm + warp * PSM_STRIDE;
                pw[m * 9 + n]           = acc[mf][0];
                pw[m * 9 + n + 1]       = acc[mf][1];
                pw[(m + 8) * 9 + n]     = acc[mf][2];
                pw[(m + 8) * 9 + n + 1] = acc[mf][3];
            }
            __syncthreads();
        } else {
            if (warp < 8) xq = __ldg(xp_ptr);
        }

        if (warp < 8) {
            float dot = 0.0f;
            if (t > 0) {
                #pragma unroll
                for (int w = 0; w < 16; w++)
                    dot += psm[w * PSM_STRIDE + lane * 9 + warp];
            }
            r_ptr[(size_t)t * HH] = fast_tanh(xq + dot);

            if (t < LL - 1) {
                asm volatile("bar.sync 1, 256;" ::: "memory");
                if (tid == 0)
                    st_release(my_flag, (unsigned)(t + 1));
            }
        }
    }
}

__global__ void rnn_init_kernel()
{
    const int i = threadIdx.x;
    if (i < 128) g_done[(i >> 1) * 32 + (i & 1)] = 0u;
}

// ---------------------------------------------------------------------------
// Launch: 7 graph nodes
// ---------------------------------------------------------------------------
extern "C" void kernel_launch(void* const* d_in, const int* in_sizes, int n_in,
                              void* d_out, int out_size)
{
    const float* x     = (const float*)d_in[0];
    const float* W_ih1 = (const float*)d_in[1];
    const float* W_hh1 = (const float*)d_in[2];
    const float* b_ih1 = (const float*)d_in[3];
    const float* b_hh1 = (const float*)d_in[4];
    const float* W_ih2 = (const float*)d_in[5];
    const float* W_hh2 = (const float*)d_in[6];
    const float* b_ih2 = (const float*)d_in[7];
    const float* b_hh2 = (const float*)d_in[8];
    const float* W1    = (const float*)d_in[9];
    const float* b1    = (const float*)d_in[10];
    const float* W2    = (const float*)d_in[11];
    const float* b2    = (const float*)d_in[12];
    float* out = (float*)d_out;

    static int attr_set = 0;
    if (!attr_set) {
        cudaFuncSetAttribute(rnn_layer_kernel,
                             cudaFuncAttributeMaxDynamicSharedMemorySize,
                             RNN_SMEM_BYTES);
        attr_set = 1;
    }

    const dim3 gBig(HH / 128, BL / 128, 1);   // (8, 128, 1)
    const dim3 gHead(OO / 128, BL / 128, 2);  // (1, 128, 2) both heads fused

    // xp = x @ W_ih1^T + b_ih1 + b_hh1
    mma_gemm<<<gBig, 256>>>(
        x, SEL_EXT, W_ih1, nullptr, SEL_XP, b_ih1, b_hh1, HH, EE,
        0, nullptr, nullptr, nullptr);
    // layer 1 recurrence
    rnn_init_kernel<<<1, 128>>>();
    rnn_layer_kernel<<<RNN_BLOCKS, 512, RNN_SMEM_BYTES>>>(SEL_R1, W_hh1);

    // xp = r1 @ W_ih2^T + b_ih2 + b_hh2
    mma_gemm<<<gBig, 256>>>(
        nullptr, SEL_R1, W_ih2, nullptr, SEL_XP, b_ih2, b_hh2, HH, HH,
        0, nullptr, nullptr, nullptr);
    // layer 2 recurrence
    rnn_init_kernel<<<1, 128>>>();
    rnn_layer_kernel<<<RNN_BLOCKS, 512, RNN_SMEM_BYTES>>>(SEL_R2, W_hh2);

    // both heads in one launch: z=0 -> y = r1@W1^T + b1 ; z=1 -> z = r2@W2^T + b2
    mma_gemm<<<gHead, 256>>>(
        nullptr, SEL_R1, W1, out, SEL_EXT, b1, nullptr, OO, HH,
        SEL_R2, W2, b2, out + (size_t)BL * OO);
}

// round 17
// speedup vs baseline: 1.2134x; 1.0082x over previous
#include <cuda_runtime.h>
#include <cuda_bf16.h>
#include <math.h>
#include <stdint.h>

// Problem dims
#define BB   32
#define LL   512
#define EE   768
#define HH   1024
#define OO   128
#define BL   (BB * LL)          // 16384

// ---------------------------------------------------------------------------
// Static scratch (allocation-free)
// ---------------------------------------------------------------------------
__device__ float g_xp[(size_t)BL * HH];
__device__ float g_r1[(size_t)BL * HH];
__device__ float g_r2[(size_t)BL * HH];

// per-producer-warp done flags: line per (batch-group, consumer-warp w):
// index = (bg*16 + w)*32 + word, word = (cg&1)*8 + producer_warp (0..7).
__device__ unsigned g_done[4 * 16 * 32];

#define SEL_EXT 0
#define SEL_R1  1
#define SEL_R2  2
#define SEL_XP  3

__device__ __forceinline__ const float* pick_src(int sel, const float* ext) {
    if (sel == SEL_R1) return g_r1;
    if (sel == SEL_R2) return g_r2;
    if (sel == SEL_XP) return g_xp;
    return ext;
}
__device__ __forceinline__ float* pick_dst(int sel, float* ext) {
    if (sel == SEL_XP) return g_xp;
    if (sel == SEL_R1) return g_r1;
    if (sel == SEL_R2) return g_r2;
    return ext;
}

// ---------------------------------------------------------------------------
// helpers
// ---------------------------------------------------------------------------
__device__ __forceinline__ uint32_t smem_to_u32(const void* p) {
    uint32_t a;
    asm("{ .reg .u64 t; cvta.to.shared.u64 t, %1; cvt.u32.u64 %0, t; }"
        : "=r"(a) : "l"(p));
    return a;
}
__device__ __forceinline__ float fast_tanh(float x) {
    float xc = fminf(fmaxf(x, -15.0f), 15.0f);
    float e  = __expf(2.0f * xc);
    return 1.0f - __fdividef(2.0f, e + 1.0f);
}
__device__ __forceinline__ void st_release(unsigned* p, unsigned v) {
    asm volatile("st.global.release.gpu.u32 [%0], %1;" :: "l"(p), "r"(v) : "memory");
}
__device__ __forceinline__ unsigned ld_acquire(const unsigned* p) {
    unsigned v;
    asm volatile("ld.global.acquire.gpu.u32 %0, [%1];" : "=r"(v) : "l"(p) : "memory");
    return v;
}

// ldmatrix / mma.sync (sm_80-baseline ISA)
#define LDSM4(r, a) \
    asm volatile("ldmatrix.sync.aligned.m8n8.x4.shared.b16 {%0,%1,%2,%3}, [%4];" \
        : "=r"((r)[0]), "=r"((r)[1]), "=r"((r)[2]), "=r"((r)[3]) : "r"(a))
#define LDSM2(r, a) \
    asm volatile("ldmatrix.sync.aligned.m8n8.x2.shared.b16 {%0,%1}, [%2];" \
        : "=r"((r)[0]), "=r"((r)[1]) : "r"(a))
#define MMA16816(d, a, b) \
    asm volatile("mma.sync.aligned.m16n8k16.row.col.f32.bf16.bf16.f32 " \
        "{%0,%1,%2,%3}, {%4,%5,%6,%7}, {%8,%9}, {%0,%1,%2,%3};" \
        : "+f"((d)[0]), "+f"((d)[1]), "+f"((d)[2]), "+f"((d)[3]) \
        : "r"((a)[0]), "r"((a)[1]), "r"((a)[2]), "r"((a)[3]), \
          "r"((b)[0]), "r"((b)[1]))

// 8 fp32 -> 8 bf16 hi (uint4) + 8 bf16 lo (uint4)
__device__ __forceinline__ void split8(const float4 v0, const float4 v1,
                                       uint4& hh, uint4& ll)
{
    float f[8] = {v0.x, v0.y, v0.z, v0.w, v1.x, v1.y, v1.z, v1.w};
    __nv_bfloat162 h[4], l[4];
    #pragma unroll
    for (int i = 0; i < 4; i++) {
        __nv_bfloat16 h0 = __float2bfloat16(f[2*i]);
        __nv_bfloat16 h1 = __float2bfloat16(f[2*i+1]);
        h[i] = __nv_bfloat162(h0, h1);
        l[i] = __nv_bfloat162(__float2bfloat16(f[2*i]   - __bfloat162float(h0)),
                              __float2bfloat16(f[2*i+1] - __bfloat162float(h1)));
    }
    hh = *(uint4*)h;
    ll = *(uint4*)l;
}

// 4 fp32 -> 4 bf16 hi (uint2) + 4 bf16 lo (uint2)
__device__ __forceinline__ void split4(const float4 v, uint2& hh, uint2& ll)
{
    __nv_bfloat16 h0 = __float2bfloat16(v.x);
    __nv_bfloat16 h1 = __float2bfloat16(v.y);
    __nv_bfloat16 h2 = __float2bfloat16(v.z);
    __nv_bfloat16 h3 = __float2bfloat16(v.w);
    __nv_bfloat162 hp0(h0, h1), hp1(h2, h3);
    __nv_bfloat162 lp0(__float2bfloat16(v.x - __bfloat162float(h0)),
                       __float2bfloat16(v.y - __bfloat162float(h1)));
    __nv_bfloat162 lp1(__float2bfloat16(v.z - __bfloat162float(h2)),
                       __float2bfloat16(v.w - __bfloat162float(h3)));
    hh.x = *(uint32_t*)&hp0; hh.y = *(uint32_t*)&hp1;
    ll.x = *(uint32_t*)&lp0; ll.y = *(uint32_t*)&lp1;
}

// ---------------------------------------------------------------------------
// HMMA GEMM — R13/R15-proven configuration (GKC=32, GPAD=40, static smem,
// 2 CTAs/SM). gridDim.z = 2 fuses the two head GEMMs (z=1 swaps pointers).
// ---------------------------------------------------------------------------
#define GKC  32
#define GPAD 40

__global__ __launch_bounds__(256) void mma_gemm(
    const float* __restrict__ Aext, int Asel,
    const float* __restrict__ B,
    float* __restrict__ Cext, int Csel,
    const float* __restrict__ bias1, const float* __restrict__ bias2,
    int Nfull, int K,
    int AselZ, const float* __restrict__ Bz,
    const float* __restrict__ biasz, float* __restrict__ Cz)
{
    const float* A = pick_src(Asel, Aext);
    float* C = pick_dst(Csel, Cext);
    if (blockIdx.z == 1) {       // fused second head
        A = pick_src(AselZ, nullptr);
        B = Bz;
        bias1 = biasz;
        C = Cz;
    }

    __shared__ __nv_bfloat16 sAh[128 * GPAD], sAl[128 * GPAD];
    __shared__ __nv_bfloat16 sBh[128 * GPAD], sBl[128 * GPAD];

    const int tid  = threadIdx.x;
    const int wid  = tid >> 5;
    const int lane = tid & 31;
    const int wm   = wid >> 2;
    const int wn   = wid & 3;
    const int m0   = blockIdx.y * 128;
    const int n0   = blockIdx.x * 128;

    float acc[4][4][4];
    #pragma unroll
    for (int i = 0; i < 4; i++)
        #pragma unroll
        for (int j = 0; j < 4; j++)
            #pragma unroll
            for (int k = 0; k < 4; k++) acc[i][j][k] = 0.0f;

    const uint32_t uAh = smem_to_u32(sAh), uAl = smem_to_u32(sAl);
    const uint32_t uBh = smem_to_u32(sBh), uBl = smem_to_u32(sBl);
    const uint32_t aoff = (uint32_t)((wm * 64 + (lane & 15)) * GPAD + (lane >> 4) * 8) * 2u;
    const uint32_t boff = (uint32_t)((wn * 32 + (lane & 7)) * GPAD + ((lane >> 3) & 1) * 8) * 2u;

    for (int k0 = 0; k0 < K; k0 += GKC) {
        #pragma unroll
        for (int p = 0; p < 4; p++) {
            const int i   = p * 256 + tid;
            const int j   = i & 511;
            const int row = j >> 2;
            const int seg = j & 3;
            const int so  = row * GPAD + seg * 8;
            if (p < 2) {
                const float* src = A + (size_t)(m0 + row) * K + k0 + seg * 8;
                float4 v0 = *(const float4*)src;
                float4 v1 = *(const float4*)(src + 4);
                uint4 hh, ll;
                split8(v0, v1, hh, ll);
                *(uint4*)&sAh[so] = hh;
                *(uint4*)&sAl[so] = ll;
            } else {
                const float* src = B + (size_t)(n0 + row) * K + k0 + seg * 8;
                float4 v0 = *(const float4*)src;
                float4 v1 = *(const float4*)(src + 4);
                uint4 hh, ll;
                split8(v0, v1, hh, ll);
                *(uint4*)&sBh[so] = hh;
                *(uint4*)&sBl[so] = ll;
            }
        }
        __syncthreads();

        #pragma unroll
        for (int ks = 0; ks < 2; ks++) {
            const uint32_t ko = (uint32_t)(ks * 16) * 2u;
            uint32_t bh[4][2], bl[4][2];
            #pragma unroll
            for (int nf = 0; nf < 4; nf++) {
                const uint32_t fo = (uint32_t)(nf * 8 * GPAD) * 2u + ko;
                LDSM2(bh[nf], uBh + boff + fo);
                LDSM2(bl[nf], uBl + boff + fo);
            }
            #pragma unroll
            for (int mf = 0; mf < 4; mf++) {
                const uint32_t fo = (uint32_t)(mf * 16 * GPAD) * 2u + ko;
                uint32_t ah[4], al[4];
                LDSM4(ah, uAh + aoff + fo);
                LDSM4(al, uAl + aoff + fo);
                #pragma unroll
                for (int nf = 0; nf < 4; nf++) {
                    MMA16816(acc[mf][nf], ah, bh[nf]);
                    MMA16816(acc[mf][nf], ah, bl[nf]);
                    MMA16816(acc[mf][nf], al, bh[nf]);
                }
            }
        }
        __syncthreads();
    }

    #pragma unroll
    for (int mf = 0; mf < 4; mf++) {
        const int mrow = m0 + wm * 64 + mf * 16 + (lane >> 2);
        #pragma unroll
        for (int nf = 0; nf < 4; nf++) {
            const int col = n0 + wn * 32 + nf * 8 + (lane & 3) * 2;
            float b0 = bias1[col], b1 = bias1[col + 1];
            if (bias2) { b0 += bias2[col]; b1 += bias2[col + 1]; }
            float2 v0 = make_float2(acc[mf][nf][0] + b0, acc[mf][nf][1] + b1);
            float2 v1 = make_float2(acc[mf][nf][2] + b0, acc[mf][nf][3] + b1);
            *(float2*)(C + (size_t)mrow * Nfull + col) = v0;
            *(float2*)(C + (size_t)(mrow + 8) * Nfull + col) = v1;
        }
    }
}

// ---------------------------------------------------------------------------
// Persistent RNN layer with HMMA inner product.
// vs R15: per-producer-warp release flags (no bar.sync), LDSM2 hoist, and a
// second uniform __syncthreads (barrier B) that orders "producers read
// psm(t)" before "any warp writes psm(t+1)" — closes the latent psm race.
// Publish happens BEFORE barrier B, so the inter-block critical path is
// unaffected by B.
// ---------------------------------------------------------------------------
#define RNN_BLOCKS 128
#define RNN_SMEM_BYTES (32 * 1028 * 4)   // 131.6KB -> forces 1 block/SM
#define IMG_PAD 1032                     // bf16 per image row
#define HW_PAD  72                       // bf16 per h row (64 data + 8 pad)
#define HW_WARP (8 * HW_PAD * 2)         // bytes per warp per (hi|lo): 1152
#define PSM_STRIDE 296                   // floats per warp region
#define PSM_OFF 40960                    // byte offset of psm (> 16*2304)

__global__ __launch_bounds__(512) void rnn_layer_kernel(
    int rsel, const float* __restrict__ W)
{
    float* r = (rsel == SEL_R1) ? g_r1 : g_r2;

    extern __shared__ char smc[];

    const int tid  = threadIdx.x;
    const int warp = tid >> 5;
    const int lane = tid & 31;
    const int bg = blockIdx.x >> 5;
    const int cg = blockIdx.x & 31;
    const int b0 = bg * 8;
    const int c0 = cg * 32;
    const int kbase = warp * 64;

    // my publish word (producers: warps 0-7); my poll line (consumer warp)
    unsigned* my_flag   = &g_done[(bg * 16 + (cg >> 1)) * 32 + (cg & 1) * 8 + warp];
    unsigned* poll_line = &g_done[(bg * 16 + warp) * 32];

    // ---- build W_hh bf16 hi/lo fragments in registers (once per layer) ----
    uint32_t wh[2][4][4], wl[2][4][4];
    {
        __nv_bfloat16* img_h = (__nv_bfloat16*)smc;
        __nv_bfloat16* img_l = (__nv_bfloat16*)(smc + 16 * IMG_PAD * 2);
        const uint32_t uih = smem_to_u32(img_h);
        const uint32_t uil = smem_to_u32(img_l);

        #pragma unroll
        for (int mf = 0; mf < 2; mf++) {
            const int row = tid >> 5;            // 0..15
            const int kk0 = (tid & 31) * 32;
            const float* wsrc = W + (size_t)(c0 + mf * 16 + row) * HH + kk0;
            #pragma unroll
            for (int j = 0; j < 8; j++) {
                float4 v = *(const float4*)(wsrc + j * 4);
                uint2 hh, ll;
                split4(v, hh, ll);
                *(uint2*)&img_h[row * IMG_PAD + kk0 + j * 4] = hh;
                *(uint2*)&img_l[row * IMG_PAD + kk0 + j * 4] = ll;
            }
            __syncthreads();
            const uint32_t ao =
                (uint32_t)((lane & 15) * IMG_PAD + kbase + (lane >> 4) * 8) * 2u;
            #pragma unroll
            for (int ks = 0; ks < 4; ks++) {
                LDSM4(wh[mf][ks], uih + ao + (uint32_t)(ks * 16) * 2u);
                LDSM4(wl[mf][ks], uil + ao + (uint32_t)(ks * 16) * 2u);
            }
            __syncthreads();
        }
    }

    // steady-state smem: h rows (16 warps x 2304B = 36864B) + psm
    char* hwbase = smc;
    float* psm   = (float*)(smc + PSM_OFF);
    __nv_bfloat16* hw_h = (__nv_bfloat16*)(hwbase + warp * (2 * HW_WARP));
    __nv_bfloat16* hw_l = (__nv_bfloat16*)(hwbase + warp * (2 * HW_WARP) + HW_WARP);
    const uint32_t uhh = smem_to_u32(hw_h);
    const uint32_t uhl = smem_to_u32(hw_l);
    const uint32_t bo =
        (uint32_t)((lane & 7) * HW_PAD + ((lane >> 3) & 1) * 8) * 2u;

    const float* xp_ptr = g_xp + ((size_t)(b0 + warp) * LL) * HH + (c0 + lane);
    float*       r_ptr  = r    + ((size_t)(b0 + warp) * LL) * HH + (c0 + lane);

    for (int t = 0; t < LL; t++) {
        float xq = 0.0f;
        if (t > 0) {
            // wait for all 16 producer warps of my two producer blocks:
            // lanes read the 16-word flag line (dup on 16-31), min via shfl_xor
            unsigned f;
            do {
                unsigned v = ld_acquire(poll_line + (lane & 15));
                #pragma unroll
                for (int m = 8; m >= 1; m >>= 1) {
                    unsigned o = __shfl_xor_sync(0xffffffffu, v, m);
                    v = (o < v) ? o : v;
                }
                f = v;
            } while (f < (unsigned)t);

            // warp-local h staging: 4 float4 per thread -> bf16 hi/lo smem
            const float* hsrc = r + (size_t)(t - 1) * HH + kbase;
            #pragma unroll
            for (int j = 0; j < 4; j++) {
                const int i  = j * 32 + lane;
                const int rr = i >> 4;            // 0..7 (batch row)
                const int qq = (i & 15) << 2;     // 0..60 (k)
                float4 v = *(const float4*)(hsrc + (size_t)(b0 + rr) * LL * HH + qq);
                uint2 hh, ll;
                split4(v, hh, ll);
                *(uint2*)&hw_h[rr * HW_PAD + qq] = hh;
                *(uint2*)&hw_l[rr * HW_PAD + qq] = ll;
            }
            __syncwarp();

            if (warp < 8) xq = __ldg(xp_ptr + (size_t)t * HH);

            float acc[2][4];
            #pragma unroll
            for (int mf = 0; mf < 2; mf++)
                #pragma unroll
                for (int i = 0; i < 4; i++) acc[mf][i] = 0.0f;

            // all 8 LDSM2 up-front, then 24 MMAs back-to-back
            uint32_t bh[4][2], bl[4][2];
            #pragma unroll
            for (int ks = 0; ks < 4; ks++) {
                const uint32_t ko = (uint32_t)(ks * 16) * 2u;
                LDSM2(bh[ks], uhh + bo + ko);
                LDSM2(bl[ks], uhl + bo + ko);
            }
            #pragma unroll
            for (int ks = 0; ks < 4; ks++) {
                #pragma unroll
                for (int mf = 0; mf < 2; mf++) {
                    MMA16816(acc[mf], wh[mf][ks], bh[ks]);
                    MMA16816(acc[mf], wh[mf][ks], bl[ks]);
                    MMA16816(acc[mf], wl[mf][ks], bh[ks]);
                }
            }

            #pragma unroll
            for (int mf = 0; mf < 2; mf++) {
                const int m = mf * 16 + (lane >> 2);
                const int n = (lane & 3) * 2;
                float* pw = psm + warp * PSM_STRIDE;
                pw[m * 9 + n]           = acc[mf][0];
                pw[m * 9 + n + 1]       = acc[mf][1];
                pw[(m + 8) * 9 + n]     = acc[mf][2];
                pw[(m + 8) * 9 + n + 1] = acc[mf][3];
            }
            __syncthreads();   // barrier A: psm(t) visible to producers
        } else {
            if (warp < 8) xq = __ldg(xp_ptr);
        }

        // producers: reduce + activation + store + per-warp publish
        if (warp < 8) {
            float dot = 0.0f;
            if (t > 0) {
                #pragma unroll
                for (int w = 0; w < 16; w++)
                    dot += psm[w * PSM_STRIDE + lane * 9 + warp];
            }
            r_ptr[(size_t)t * HH] = fast_tanh(xq + dot);

            if (t < LL - 1) {
                __syncwarp();                  // order this warp's STGs
                if (lane == 0)
                    st_release(my_flag, (unsigned)(t + 1));
            }
        }

        // barrier B: producers finished READING psm(t) before anyone can
        // write psm(t+1). Publish already happened -> off the critical path.
        if (t > 0 && t < LL - 1)
            __syncthreads();
    }
}

// reset all per-warp flags (before each rnn layer -> deterministic replays)
__global__ void rnn_init_kernel()
{
    const int i = blockIdx.x * blockDim.x + threadIdx.x;   // 0..1023
    if (i < 1024) g_done[(i >> 4) * 32 + (i & 15)] = 0u;
}

// ---------------------------------------------------------------------------
// Launch: 7 graph nodes
// ---------------------------------------------------------------------------
extern "C" void kernel_launch(void* const* d_in, const int* in_sizes, int n_in,
                              void* d_out, int out_size)
{
    const float* x     = (const float*)d_in[0];
    const float* W_ih1 = (const float*)d_in[1];
    const float* W_hh1 = (const float*)d_in[2];
    const float* b_ih1 = (const float*)d_in[3];
    const float* b_hh1 = (const float*)d_in[4];
    const float* W_ih2 = (const float*)d_in[5];
    const float* W_hh2 = (const float*)d_in[6];
    const float* b_ih2 = (const float*)d_in[7];
    const float* b_hh2 = (const float*)d_in[8];
    const float* W1    = (const float*)d_in[9];
    const float* b1    = (const float*)d_in[10];
    const float* W2    = (const float*)d_in[11];
    const float* b2    = (const float*)d_in[12];
    float* out = (float*)d_out;

    static int attr_set = 0;
    if (!attr_set) {
        cudaFuncSetAttribute(rnn_layer_kernel,
                             cudaFuncAttributeMaxDynamicSharedMemorySize,
                             RNN_SMEM_BYTES);
        attr_set = 1;
    }

    const dim3 gBig(HH / 128, BL / 128, 1);   // (8, 128, 1)
    const dim3 gHead(OO / 128, BL / 128, 2);  // (1, 128, 2) both heads fused

    // xp = x @ W_ih1^T + b_ih1 + b_hh1
    mma_gemm<<<gBig, 256>>>(
        x, SEL_EXT, W_ih1, nullptr, SEL_XP, b_ih1, b_hh1, HH, EE,
        0, nullptr, nullptr, nullptr);
    // layer 1 recurrence
    rnn_init_kernel<<<2, 512>>>();
    rnn_layer_kernel<<<RNN_BLOCKS, 512, RNN_SMEM_BYTES>>>(SEL_R1, W_hh1);

    // xp = r1 @ W_ih2^T + b_ih2 + b_hh2
    mma_gemm<<<gBig, 256>>>(
        nullptr, SEL_R1, W_ih2, nullptr, SEL_XP, b_ih2, b_hh2, HH, HH,
        0, nullptr, nullptr, nullptr);
    // layer 2 recurrence
    rnn_init_kernel<<<2, 512>>>();
    rnn_layer_kernel<<<RNN_BLOCKS, 512, RNN_SMEM_BYTES>>>(SEL_R2, W_hh2);

    // both heads in one launch: z=0 -> y = r1@W1^T + b1 ; z=1 -> z = r2@W2^T + b2
    mma_gemm<<<gHead, 256>>>(
        nullptr, SEL_R1, W1, out, SEL_EXT, b1, nullptr, OO, HH,
        SEL_R2, W2, b2, out + (size_t)BL * OO);
}